// round 1
// baseline (speedup 1.0000x reference)
#include <cuda_runtime.h>

// ---------------------------------------------------------------------------
// ChildSumTreeLSTM on a complete binary tree, depth 17, D_IN = H = 128.
// Structure:
//   1) gemm_x_kernel x4 : X_g = x @ W_g + b_g  for all N nodes      (17.2 G FMA)
//   2) leaf_kernel      : elementwise leaf cells                    (mem bound)
//   3) level_kernel x17 : bottom-up recurrence, 5 128x128 matvecs/node
//   4) out_kernel       : write [h_root, c_root]
// All fp32. Scratch in __device__ globals (no allocations).
// ---------------------------------------------------------------------------

#define DEPTH   17
#define HH      128
#define NNODES  ((1 << (DEPTH + 1)) - 1)        // 262143
#define NH      33554304L                        // NNODES * HH

__device__ float g_X[4 * 33554304L];             // pre-activations, gate-major: i,f,o,u
__device__ float g_h[33554304L];                 // hidden per node
__device__ float g_c[33554304L];                 // cell per node

__device__ __forceinline__ float sigf(float v) { return 1.0f / (1.0f + expf(-v)); }

// ---------------------------------------------------------------------------
// Kernel 1: X = x @ W + b for one gate. Block: 64 rows x 128 cols.
// smem: x tile (64x128) + W (128x128) = 96 KB dynamic.
// Thread tile: 8 rows x 4 cols (256 threads).
// ---------------------------------------------------------------------------
__global__ void __launch_bounds__(256) gemm_x_kernel(
    const float* __restrict__ x, const float* __restrict__ W,
    const float* __restrict__ b, int gate)
{
    extern __shared__ float sm[];
    float* xs = sm;                 // 64 * 128
    float* ws = sm + 64 * HH;       // 128 * 128

    const int tid = threadIdx.x;
    const int r0  = blockIdx.x * 64;

    // load x tile (float4), guard tail rows
    for (int f = tid; f < 2048; f += 256) {
        int row = f >> 5, wq = f & 31;
        float4 v = make_float4(0.f, 0.f, 0.f, 0.f);
        if (r0 + row < NNODES)
            v = *(const float4*)(x + (long)(r0 + row) * HH + wq * 4);
        *(float4*)(xs + row * HH + wq * 4) = v;
    }
    // load full W (row-major [k][h])
    for (int f = tid; f < 4096; f += 256)
        ((float4*)ws)[f] = ((const float4*)W)[f];
    __syncthreads();

    const int rg = tid >> 5;
    const int c0 = (tid & 31) * 4;
    float acc[8][4];
#pragma unroll
    for (int r = 0; r < 8; ++r) { acc[r][0] = acc[r][1] = acc[r][2] = acc[r][3] = 0.f; }

    const float* xrow = xs + rg * 8 * HH;
#pragma unroll 4
    for (int k = 0; k < 128; ++k) {
        float4 w = *(const float4*)(ws + k * HH + c0);
#pragma unroll
        for (int r = 0; r < 8; ++r) {
            float xv = xrow[r * HH + k];
            acc[r][0] += xv * w.x; acc[r][1] += xv * w.y;
            acc[r][2] += xv * w.z; acc[r][3] += xv * w.w;
        }
    }

    float4 bb = *(const float4*)(b + c0);
    float* out = g_X + (long)gate * NH;
#pragma unroll
    for (int r = 0; r < 8; ++r) {
        int row = r0 + rg * 8 + r;
        if (row < NNODES) {
            float4 v = make_float4(acc[r][0] + bb.x, acc[r][1] + bb.y,
                                   acc[r][2] + bb.z, acc[r][3] + bb.w);
            *(float4*)(out + (long)row * HH + c0) = v;
        }
    }
}

// ---------------------------------------------------------------------------
// Kernel 2: leaves (level DEPTH). No children: c = sig(Xi)*tanh(Xu), h = sig(Xo)*tanh(c).
// ---------------------------------------------------------------------------
__global__ void leaf_kernel()
{
    const long base = ((1L << DEPTH) - 1) * HH;        // first leaf element
    long e = base + (long)blockIdx.x * blockDim.x + threadIdx.x;
    float i = sigf(g_X[e]);                 // gate i at offset 0
    float o = sigf(g_X[2 * NH + e]);        // gate o
    float u = tanhf(g_X[3 * NH + e]);       // gate u
    float c = i * u;
    g_c[e] = c;
    g_h[e] = o * tanhf(c);
}

// ---------------------------------------------------------------------------
// Tile GEMM helper: acc[8][4] = src_rows @ us, thread owns rows j0..j0+7
// (mapped through row*rmul+radd) and cols c0..c0+3. src/us in shared memory.
// ---------------------------------------------------------------------------
__device__ __forceinline__ void tile_gemm(
    float acc[8][4], const float* __restrict__ src,
    int j0, int rmul, int radd, const float* __restrict__ us, int c0)
{
#pragma unroll
    for (int r = 0; r < 8; ++r) { acc[r][0] = acc[r][1] = acc[r][2] = acc[r][3] = 0.f; }
#pragma unroll 4
    for (int k = 0; k < 128; ++k) {
        float4 w = *(const float4*)(us + k * HH + c0);
#pragma unroll
        for (int r = 0; r < 8; ++r) {
            float hv = src[((j0 + r) * rmul + radd) * HH + k];
            acc[r][0] += hv * w.x; acc[r][1] += hv * w.y;
            acc[r][2] += hv * w.z; acc[r][3] += hv * w.w;
        }
    }
}

// ---------------------------------------------------------------------------
// Kernel 3: one internal level. Block: 64 parents. smem = child-h tile (128x128)
// + h_tilde (64x128) + U staging (128x128) = 160 KB dynamic.
// Gate order u -> i -> f(child0) -> f(child1) -> o so only 2 live reg tiles.
// ---------------------------------------------------------------------------
__global__ void __launch_bounds__(256) level_kernel(
    int sl, int nl,
    const float* __restrict__ U_i, const float* __restrict__ U_f,
    const float* __restrict__ U_o, const float* __restrict__ U_u)
{
    extern __shared__ float sm[];
    float* hch = sm;                        // 128x128 child hidden
    float* hts = sm + 16384;                // 64x128  child-sum
    float* us  = sm + 16384 + 8192;         // 128x128 U staging

    const int tid = threadIdx.x;
    const int p0  = blockIdx.x * 64;
    const long cs = 2L * sl + 1;            // first child node of this level

    // child h tile: children of parents p0..p0+63 are 128 CONTIGUOUS rows of g_h
    const long crow0   = cs + 2L * p0;
    const int  maxcrow = 2 * nl - 2 * p0;
    for (int f = tid; f < 4096; f += 256) {
        int row = f >> 5, wq = f & 31;
        float4 v = make_float4(0.f, 0.f, 0.f, 0.f);
        if (row < maxcrow)
            v = *(const float4*)(g_h + (crow0 + row) * HH + wq * 4);
        *(float4*)(hch + row * HH + wq * 4) = v;
    }
    __syncthreads();
    // h_tilde = sum of the two children
    for (int f = tid; f < 2048; f += 256) {
        int j = f >> 5, wq = f & 31;
        float4 a = *(const float4*)(hch + (2 * j)     * HH + wq * 4);
        float4 b = *(const float4*)(hch + (2 * j + 1) * HH + wq * 4);
        *(float4*)(hts + j * HH + wq * 4) =
            make_float4(a.x + b.x, a.y + b.y, a.z + b.z, a.w + b.w);
    }

    const int rg = tid >> 5;
    const int c0 = (tid & 31) * 4;
    const int j0 = rg * 8;
    float cacc[8][4], acc[8][4];

#define LOAD_U(SRC) do { __syncthreads();                                   \
        for (int f = tid; f < 4096; f += 256)                               \
            ((float4*)us)[f] = ((const float4*)(SRC))[f];                   \
        __syncthreads(); } while (0)
#define X4(G, NODE) (*(const float4*)(g_X + (long)(G) * NH + (long)(NODE) * HH + c0))

    // ---- u gate: cacc = tanh(Xu + h~ @ U_u) ----
    LOAD_U(U_u);
    tile_gemm(acc, hts, j0, 1, 0, us, c0);
#pragma unroll
    for (int r = 0; r < 8; ++r) {
        float4 xg = X4(3, sl + p0 + j0 + r);
        cacc[r][0] = tanhf(acc[r][0] + xg.x);
        cacc[r][1] = tanhf(acc[r][1] + xg.y);
        cacc[r][2] = tanhf(acc[r][2] + xg.z);
        cacc[r][3] = tanhf(acc[r][3] + xg.w);
    }
    // ---- i gate: cacc = sig(Xi + h~ @ U_i) * cacc ----
    LOAD_U(U_i);
    tile_gemm(acc, hts, j0, 1, 0, us, c0);
#pragma unroll
    for (int r = 0; r < 8; ++r) {
        float4 xg = X4(0, sl + p0 + j0 + r);
        cacc[r][0] *= sigf(acc[r][0] + xg.x);
        cacc[r][1] *= sigf(acc[r][1] + xg.y);
        cacc[r][2] *= sigf(acc[r][2] + xg.z);
        cacc[r][3] *= sigf(acc[r][3] + xg.w);
    }
    // ---- f gates (U_f loaded once for both children) ----
    LOAD_U(U_f);
    tile_gemm(acc, hch, j0, 2, 0, us, c0);          // child 0 rows
#pragma unroll
    for (int r = 0; r < 8; ++r) {
        long ch = cs + 2L * (p0 + j0 + r);
        float4 xf = X4(1, sl + p0 + j0 + r);
        float4 cc = *(const float4*)(g_c + ch * HH + c0);
        cacc[r][0] += sigf(acc[r][0] + xf.x) * cc.x;
        cacc[r][1] += sigf(acc[r][1] + xf.y) * cc.y;
        cacc[r][2] += sigf(acc[r][2] + xf.z) * cc.z;
        cacc[r][3] += sigf(acc[r][3] + xf.w) * cc.w;
    }
    tile_gemm(acc, hch, j0, 2, 1, us, c0);          // child 1 rows
#pragma unroll
    for (int r = 0; r < 8; ++r) {
        long ch = cs + 2L * (p0 + j0 + r) + 1;
        float4 xf = X4(1, sl + p0 + j0 + r);
        float4 cc = *(const float4*)(g_c + ch * HH + c0);
        cacc[r][0] += sigf(acc[r][0] + xf.x) * cc.x;
        cacc[r][1] += sigf(acc[r][1] + xf.y) * cc.y;
        cacc[r][2] += sigf(acc[r][2] + xf.z) * cc.z;
        cacc[r][3] += sigf(acc[r][3] + xf.w) * cc.w;
    }
    // ---- o gate + store ----
    LOAD_U(U_o);
    tile_gemm(acc, hts, j0, 1, 0, us, c0);
#pragma unroll
    for (int r = 0; r < 8; ++r) {
        int p = p0 + j0 + r;
        if (p < nl) {
            long node = sl + p;
            float4 xg = X4(2, node);
            float4 cv = make_float4(cacc[r][0], cacc[r][1], cacc[r][2], cacc[r][3]);
            float4 hv = make_float4(sigf(acc[r][0] + xg.x) * tanhf(cv.x),
                                    sigf(acc[r][1] + xg.y) * tanhf(cv.y),
                                    sigf(acc[r][2] + xg.z) * tanhf(cv.z),
                                    sigf(acc[r][3] + xg.w) * tanhf(cv.w));
            *(float4*)(g_c + node * HH + c0) = cv;
            *(float4*)(g_h + node * HH + c0) = hv;
        }
    }
#undef LOAD_U
#undef X4
}

// ---------------------------------------------------------------------------
// Kernel 4: out = [h_root(128), c_root(128)]
// ---------------------------------------------------------------------------
__global__ void out_kernel(float* __restrict__ out)
{
    int t = threadIdx.x;
    out[t] = (t < 128) ? g_h[t] : g_c[t - 128];
}

// ---------------------------------------------------------------------------
extern "C" void kernel_launch(void* const* d_in, const int* in_sizes, int n_in,
                              void* d_out, int out_size)
{
    const float* x   = (const float*)d_in[0];
    const float* W_i = (const float*)d_in[1];
    const float* b_i = (const float*)d_in[2];
    const float* U_i = (const float*)d_in[3];
    const float* W_f = (const float*)d_in[4];
    const float* b_f = (const float*)d_in[5];
    const float* U_f = (const float*)d_in[6];
    const float* W_o = (const float*)d_in[7];
    const float* b_o = (const float*)d_in[8];
    const float* U_o = (const float*)d_in[9];
    const float* W_u = (const float*)d_in[10];
    const float* b_u = (const float*)d_in[11];
    const float* U_u = (const float*)d_in[12];

    cudaFuncSetAttribute(gemm_x_kernel, cudaFuncAttributeMaxDynamicSharedMemorySize, 98304);
    cudaFuncSetAttribute(level_kernel,  cudaFuncAttributeMaxDynamicSharedMemorySize, 163840);

    const int rowBlocks = (NNODES + 63) / 64;   // 4096
    gemm_x_kernel<<<rowBlocks, 256, 98304>>>(x, W_i, b_i, 0);
    gemm_x_kernel<<<rowBlocks, 256, 98304>>>(x, W_f, b_f, 1);
    gemm_x_kernel<<<rowBlocks, 256, 98304>>>(x, W_o, b_o, 2);
    gemm_x_kernel<<<rowBlocks, 256, 98304>>>(x, W_u, b_u, 3);

    leaf_kernel<<<(1 << DEPTH) * HH / 256, 256>>>();   // 65536 blocks

    for (int l = DEPTH - 1; l >= 0; --l) {
        int nl = 1 << l;
        int sl = nl - 1;
        int blocks = (nl + 63) / 64;
        level_kernel<<<blocks, 256, 163840>>>(sl, nl, U_i, U_f, U_o, U_u);
    }

    out_kernel<<<1, 256>>>((float*)d_out);
}

// round 2
// speedup vs baseline: 1.0297x; 1.0297x over previous
#include <cuda_runtime.h>

// ---------------------------------------------------------------------------
// ChildSumTreeLSTM, complete binary tree depth 17, D_IN = H = 128. fp32.
// R2: packed fma.rn.f32x2 inner loops, tail-aware level kernels, fast act.
// ---------------------------------------------------------------------------

#define DEPTH   17
#define HH      128
#define NNODES  ((1 << (DEPTH + 1)) - 1)        // 262143
#define NH      33554304L                        // NNODES * HH

__device__ float g_X[4 * 33554304L];             // gate-major: i,f,o,u
__device__ float g_h[33554304L];
__device__ float g_c[33554304L];

typedef unsigned long long u64;

__device__ __forceinline__ u64 pk2(float a, float b) {
    u64 r; asm("mov.b64 %0, {%1, %2};" : "=l"(r) : "f"(a), "f"(b)); return r;
}
__device__ __forceinline__ void fma2(u64& d, u64 a, u64 b) {
    asm("fma.rn.f32x2 %0, %1, %2, %0;" : "+l"(d) : "l"(a), "l"(b));
}
__device__ __forceinline__ float2 up2(u64 v) {
    float2 f; asm("mov.b64 {%0, %1}, %2;" : "=f"(f.x), "=f"(f.y) : "l"(v)); return f;
}
__device__ __forceinline__ float sigf(float v)  { return 1.0f / (1.0f + __expf(-v)); }
__device__ __forceinline__ float tanhx(float v) {
    float r; asm("tanh.approx.f32 %0, %1;" : "=f"(r) : "f"(v)); return r;
}

// ---------------------------------------------------------------------------
// Packed tile GEMM: acc[RPT][4] (u64 = 2 cols each) += src_rows @ us.
// Thread owns RPT rows (r0 + r*rstep) and 8 cols starting at c0.
// Per 4k: RPT+8 LDS.128, 4*RPT packs, 16*RPT FFMA2.
// ---------------------------------------------------------------------------
template<int RPT>
__device__ __forceinline__ void tgemm(u64 acc[RPT][4], const float* __restrict__ src,
                                      int r0, int rstep,
                                      const float* __restrict__ us, int c0)
{
#pragma unroll
    for (int r = 0; r < RPT; ++r) { acc[r][0] = acc[r][1] = acc[r][2] = acc[r][3] = 0ULL; }
#pragma unroll 2
    for (int k0 = 0; k0 < 128; k0 += 4) {
        float4 xv[RPT];
#pragma unroll
        for (int r = 0; r < RPT; ++r)
            xv[r] = *(const float4*)(src + (r0 + r * rstep) * HH + k0);
#pragma unroll
        for (int kk = 0; kk < 4; ++kk) {
            ulonglong2 wa = *(const ulonglong2*)(us + (k0 + kk) * HH + c0);
            ulonglong2 wb = *(const ulonglong2*)(us + (k0 + kk) * HH + c0 + 4);
#pragma unroll
            for (int r = 0; r < RPT; ++r) {
                float xk = (kk == 0) ? xv[r].x : (kk == 1) ? xv[r].y
                         : (kk == 2) ? xv[r].z : xv[r].w;
                u64 x2 = pk2(xk, xk);
                fma2(acc[r][0], x2, wa.x); fma2(acc[r][1], x2, wa.y);
                fma2(acc[r][2], x2, wb.x); fma2(acc[r][3], x2, wb.y);
            }
        }
    }
}

// ---------------------------------------------------------------------------
// X = x @ W_g + b_g for gate g = blockIdx.y. Tile 64 rows x 128 cols,
// 256 threads = 16 trows (4 rows each) x 16 tcols (8 cols each). smem 96KB.
// ---------------------------------------------------------------------------
__global__ void __launch_bounds__(256) gemm_x_kernel(
    const float* __restrict__ x,
    const float* __restrict__ W_i, const float* __restrict__ b_i,
    const float* __restrict__ W_f, const float* __restrict__ b_f,
    const float* __restrict__ W_o, const float* __restrict__ b_o,
    const float* __restrict__ W_u, const float* __restrict__ b_u)
{
    const int gate = blockIdx.y;
    const float* W = (gate == 0) ? W_i : (gate == 1) ? W_f : (gate == 2) ? W_o : W_u;
    const float* b = (gate == 0) ? b_i : (gate == 1) ? b_f : (gate == 2) ? b_o : b_u;

    extern __shared__ float sm[];
    float* xs = sm;               // 64 x 128
    float* ws = sm + 64 * HH;     // 128 x 128

    const int tid = threadIdx.x;
    const int r0  = blockIdx.x * 64;

    for (int f = tid; f < 2048; f += 256) {
        int row = f >> 5, wq = f & 31;
        float4 v = make_float4(0.f, 0.f, 0.f, 0.f);
        if (r0 + row < NNODES)
            v = *(const float4*)(x + (long)(r0 + row) * HH + wq * 4);
        *(float4*)(xs + row * HH + wq * 4) = v;
    }
    for (int f = tid; f < 4096; f += 256)
        ((float4*)ws)[f] = ((const float4*)W)[f];
    __syncthreads();

    const int trow = tid >> 4;
    const int c0   = (tid & 15) * 8;

    u64 acc[4][4];
    tgemm<4>(acc, xs, trow * 4, 1, ws, c0);

    float4 ba = *(const float4*)(b + c0);
    float4 bb = *(const float4*)(b + c0 + 4);
    float* out = g_X + (long)gate * NH;
#pragma unroll
    for (int r = 0; r < 4; ++r) {
        int row = r0 + trow * 4 + r;
        if (row < NNODES) {
            float2 p0 = up2(acc[r][0]), p1 = up2(acc[r][1]);
            float2 p2 = up2(acc[r][2]), p3 = up2(acc[r][3]);
            float4 va = make_float4(p0.x + ba.x, p0.y + ba.y, p1.x + ba.z, p1.y + ba.w);
            float4 vb = make_float4(p2.x + bb.x, p2.y + bb.y, p3.x + bb.z, p3.y + bb.w);
            *(float4*)(out + (long)row * HH + c0)     = va;
            *(float4*)(out + (long)row * HH + c0 + 4) = vb;
        }
    }
}

// ---------------------------------------------------------------------------
// Leaves: c = sig(Xi)*tanh(Xu); h = sig(Xo)*tanh(c). float4 per thread.
// ---------------------------------------------------------------------------
__global__ void leaf_kernel()
{
    const long base = ((1L << DEPTH) - 1) * HH;
    long e = base + ((long)blockIdx.x * blockDim.x + threadIdx.x) * 4;
    float4 xi = *(const float4*)(g_X + e);
    float4 xo = *(const float4*)(g_X + 2 * NH + e);
    float4 xu = *(const float4*)(g_X + 3 * NH + e);
    float4 cv, hv;
    cv.x = sigf(xi.x) * tanhx(xu.x); hv.x = sigf(xo.x) * tanhx(cv.x);
    cv.y = sigf(xi.y) * tanhx(xu.y); hv.y = sigf(xo.y) * tanhx(cv.y);
    cv.z = sigf(xi.z) * tanhx(xu.z); hv.z = sigf(xo.z) * tanhx(cv.z);
    cv.w = sigf(xi.w) * tanhx(xu.w); hv.w = sigf(xo.w) * tanhx(cv.w);
    *(float4*)(g_c + e) = cv;
    *(float4*)(g_h + e) = hv;
}

// ---------------------------------------------------------------------------
// Internal level, TP = 16*RPT parents per block, 256 threads.
// smem: child-h (2*TP x 128) + h_tilde (TP x 128) + U stage (128 x 128).
// RPT=2 -> 112 KB (2 blocks/SM); RPT=1 -> 88 KB (2 blocks/SM).
// ---------------------------------------------------------------------------
template<int RPT>
__global__ void __launch_bounds__(256) level_kernel(
    int sl,
    const float* __restrict__ U_i, const float* __restrict__ U_f,
    const float* __restrict__ U_o, const float* __restrict__ U_u)
{
    constexpr int TP = 16 * RPT;
    extern __shared__ float sm[];
    float* hch = sm;                         // 2*TP x 128
    float* hts = sm + 2 * TP * HH;           // TP x 128
    float* us  = hts + TP * HH;              // 128 x 128

    const int tid  = threadIdx.x;
    const int trow = tid >> 4;
    const int c0   = (tid & 15) * 8;
    const int p0   = blockIdx.x * TP;
    const long cs  = 2L * sl + 1;
    const long crow0 = cs + 2L * p0;

    for (int f = tid; f < 2 * TP * 32; f += 256) {
        int row = f >> 5, wq = f & 31;
        *(float4*)(hch + row * HH + wq * 4) =
            *(const float4*)(g_h + (crow0 + row) * HH + wq * 4);
    }
    __syncthreads();
    for (int f = tid; f < TP * 32; f += 256) {
        int j = f >> 5, wq = f & 31;
        float4 a = *(const float4*)(hch + (2 * j) * HH + wq * 4);
        float4 b = *(const float4*)(hch + (2 * j + 1) * HH + wq * 4);
        *(float4*)(hts + j * HH + wq * 4) =
            make_float4(a.x + b.x, a.y + b.y, a.z + b.z, a.w + b.w);
    }

    u64 acc[RPT][4];
    float cacc[RPT][8];
    float a[8];

#define LOAD_U(SRC) do { __syncthreads();                                   \
        for (int f = tid; f < 4096; f += 256)                               \
            ((float4*)us)[f] = ((const float4*)(SRC))[f];                   \
        __syncthreads(); } while (0)
#define UNP(R) { float2 q0 = up2(acc[R][0]), q1 = up2(acc[R][1]),           \
                        q2 = up2(acc[R][2]), q3 = up2(acc[R][3]);           \
                 a[0]=q0.x; a[1]=q0.y; a[2]=q1.x; a[3]=q1.y;                \
                 a[4]=q2.x; a[5]=q2.y; a[6]=q3.x; a[7]=q3.y; }
#define XG(G, P) (g_X + (long)(G) * NH + (long)(sl + (P)) * HH + c0)

    // ---- u: cacc = tanh(Xu + h~ @ U_u) ----
    LOAD_U(U_u);
    tgemm<RPT>(acc, hts, trow * RPT, 1, us, c0);
#pragma unroll
    for (int r = 0; r < RPT; ++r) {
        UNP(r);
        const float* xp = XG(3, p0 + trow * RPT + r);
        float4 xa = *(const float4*)xp, xb = *(const float4*)(xp + 4);
        cacc[r][0] = tanhx(a[0] + xa.x); cacc[r][1] = tanhx(a[1] + xa.y);
        cacc[r][2] = tanhx(a[2] + xa.z); cacc[r][3] = tanhx(a[3] + xa.w);
        cacc[r][4] = tanhx(a[4] + xb.x); cacc[r][5] = tanhx(a[5] + xb.y);
        cacc[r][6] = tanhx(a[6] + xb.z); cacc[r][7] = tanhx(a[7] + xb.w);
    }
    // ---- i: cacc *= sig(Xi + h~ @ U_i) ----
    LOAD_U(U_i);
    tgemm<RPT>(acc, hts, trow * RPT, 1, us, c0);
#pragma unroll
    for (int r = 0; r < RPT; ++r) {
        UNP(r);
        const float* xp = XG(0, p0 + trow * RPT + r);
        float4 xa = *(const float4*)xp, xb = *(const float4*)(xp + 4);
        cacc[r][0] *= sigf(a[0] + xa.x); cacc[r][1] *= sigf(a[1] + xa.y);
        cacc[r][2] *= sigf(a[2] + xa.z); cacc[r][3] *= sigf(a[3] + xa.w);
        cacc[r][4] *= sigf(a[4] + xb.x); cacc[r][5] *= sigf(a[5] + xb.y);
        cacc[r][6] *= sigf(a[6] + xb.z); cacc[r][7] *= sigf(a[7] + xb.w);
    }
    // ---- f gates: U_f staged once, both children ----
    LOAD_U(U_f);
#pragma unroll
    for (int child = 0; child < 2; ++child) {
        tgemm<RPT>(acc, hch, 2 * trow * RPT + child, 2, us, c0);
#pragma unroll
        for (int r = 0; r < RPT; ++r) {
            UNP(r);
            int p = p0 + trow * RPT + r;
            const float* xp = XG(1, p);
            float4 xa = *(const float4*)xp, xb = *(const float4*)(xp + 4);
            const float* cp = g_c + (cs + 2L * p + child) * HH + c0;
            float4 ca = *(const float4*)cp, cb = *(const float4*)(cp + 4);
            cacc[r][0] += sigf(a[0] + xa.x) * ca.x;
            cacc[r][1] += sigf(a[1] + xa.y) * ca.y;
            cacc[r][2] += sigf(a[2] + xa.z) * ca.z;
            cacc[r][3] += sigf(a[3] + xa.w) * ca.w;
            cacc[r][4] += sigf(a[4] + xb.x) * cb.x;
            cacc[r][5] += sigf(a[5] + xb.y) * cb.y;
            cacc[r][6] += sigf(a[6] + xb.z) * cb.z;
            cacc[r][7] += sigf(a[7] + xb.w) * cb.w;
        }
    }
    // ---- o + store ----
    LOAD_U(U_o);
    tgemm<RPT>(acc, hts, trow * RPT, 1, us, c0);
#pragma unroll
    for (int r = 0; r < RPT; ++r) {
        UNP(r);
        long node = sl + p0 + trow * RPT + r;
        const float* xp = g_X + 2 * NH + node * HH + c0;
        float4 xa = *(const float4*)xp, xb = *(const float4*)(xp + 4);
        float4 cva = make_float4(cacc[r][0], cacc[r][1], cacc[r][2], cacc[r][3]);
        float4 cvb = make_float4(cacc[r][4], cacc[r][5], cacc[r][6], cacc[r][7]);
        float4 hva = make_float4(sigf(a[0] + xa.x) * tanhx(cva.x),
                                 sigf(a[1] + xa.y) * tanhx(cva.y),
                                 sigf(a[2] + xa.z) * tanhx(cva.z),
                                 sigf(a[3] + xa.w) * tanhx(cva.w));
        float4 hvb = make_float4(sigf(a[4] + xb.x) * tanhx(cvb.x),
                                 sigf(a[5] + xb.y) * tanhx(cvb.y),
                                 sigf(a[6] + xb.z) * tanhx(cvb.z),
                                 sigf(a[7] + xb.w) * tanhx(cvb.w));
        *(float4*)(g_c + node * HH + c0)     = cva;
        *(float4*)(g_c + node * HH + c0 + 4) = cvb;
        *(float4*)(g_h + node * HH + c0)     = hva;
        *(float4*)(g_h + node * HH + c0 + 4) = hvb;
    }
#undef LOAD_U
#undef UNP
#undef XG
}

// ---------------------------------------------------------------------------
// Small levels (nl <= 1024): one parent per block, 512 threads.
// 5 matvecs split 4-way along k, smem reduce, then 128-thread combine.
// ---------------------------------------------------------------------------
__global__ void __launch_bounds__(512) small_level_kernel(
    int sl,
    const float* __restrict__ U_i, const float* __restrict__ U_f,
    const float* __restrict__ U_o, const float* __restrict__ U_u)
{
    __shared__ float hs[3 * 128];            // h~, h0, h1
    __shared__ float part[5][4][128];

    const int t = threadIdx.x;
    const long node = sl + blockIdx.x;
    const long ch0  = 2 * node + 1;

    if (t < 128) {
        float h0 = g_h[ch0 * HH + t];
        float h1 = g_h[(ch0 + 1) * HH + t];
        hs[128 + t] = h0; hs[256 + t] = h1; hs[t] = h0 + h1;
    }
    __syncthreads();

    const int col = t & 127;
    const int kb  = (t >> 7) * 32;
    const int ks  = t >> 7;

#define JOB(J, SOFF, U) { const float* s = hs + (SOFF) * 128; float av = 0.f;  \
        _Pragma("unroll 8")                                                    \
        for (int k = 0; k < 32; ++k) av += s[kb + k] * (U)[(kb + k) * HH + col]; \
        part[J][ks][col] = av; }
    JOB(0, 0, U_i)
    JOB(1, 0, U_o)
    JOB(2, 0, U_u)
    JOB(3, 1, U_f)
    JOB(4, 2, U_f)
#undef JOB
    __syncthreads();

    if (t < 128) {
        float yi  = part[0][0][t] + part[0][1][t] + part[0][2][t] + part[0][3][t];
        float yo  = part[1][0][t] + part[1][1][t] + part[1][2][t] + part[1][3][t];
        float yu  = part[2][0][t] + part[2][1][t] + part[2][2][t] + part[2][3][t];
        float yf0 = part[3][0][t] + part[3][1][t] + part[3][2][t] + part[3][3][t];
        float yf1 = part[4][0][t] + part[4][1][t] + part[4][2][t] + part[4][3][t];
        long e = node * HH + t;
        float xf = g_X[NH + e];
        float iv = sigf(g_X[e] + yi);
        float ov = sigf(g_X[2 * NH + e] + yo);
        float uv = tanhx(g_X[3 * NH + e] + yu);
        float c  = iv * uv + sigf(xf + yf0) * g_c[ch0 * HH + t]
                           + sigf(xf + yf1) * g_c[(ch0 + 1) * HH + t];
        g_c[e] = c;
        g_h[e] = ov * tanhx(c);
    }
}

__global__ void out_kernel(float* __restrict__ out)
{
    int t = threadIdx.x;
    out[t] = (t < 128) ? g_h[t] : g_c[t - 128];
}

// ---------------------------------------------------------------------------
extern "C" void kernel_launch(void* const* d_in, const int* in_sizes, int n_in,
                              void* d_out, int out_size)
{
    const float* x   = (const float*)d_in[0];
    const float* W_i = (const float*)d_in[1];
    const float* b_i = (const float*)d_in[2];
    const float* U_i = (const float*)d_in[3];
    const float* W_f = (const float*)d_in[4];
    const float* b_f = (const float*)d_in[5];
    const float* U_f = (const float*)d_in[6];
    const float* W_o = (const float*)d_in[7];
    const float* b_o = (const float*)d_in[8];
    const float* U_o = (const float*)d_in[9];
    const float* W_u = (const float*)d_in[10];
    const float* b_u = (const float*)d_in[11];
    const float* U_u = (const float*)d_in[12];

    static int attr_done = 0;
    (void)attr_done;
    cudaFuncSetAttribute(gemm_x_kernel,   cudaFuncAttributeMaxDynamicSharedMemorySize, 98304);
    cudaFuncSetAttribute(level_kernel<2>, cudaFuncAttributeMaxDynamicSharedMemorySize, 114688);
    cudaFuncSetAttribute(level_kernel<1>, cudaFuncAttributeMaxDynamicSharedMemorySize, 90112);

    dim3 gg((NNODES + 63) / 64, 4);     // 4096 x 4 gates
    gemm_x_kernel<<<gg, 256, 98304>>>(x, W_i, b_i, W_f, b_f, W_o, b_o, W_u, b_u);

    leaf_kernel<<<(1 << DEPTH) * HH / 4 / 256, 256>>>();   // 16384 blocks

    for (int l = DEPTH - 1; l >= 0; --l) {
        int nl = 1 << l;
        int sl = nl - 1;
        if (l >= 13)
            level_kernel<2><<<nl / 32, 256, 114688>>>(sl, U_i, U_f, U_o, U_u);
        else if (l >= 11)
            level_kernel<1><<<nl / 16, 256, 90112>>>(sl, U_i, U_f, U_o, U_u);
        else
            small_level_kernel<<<nl, 512>>>(sl, U_i, U_f, U_o, U_u);
    }

    out_kernel<<<1, 256>>>((float*)d_out);
}

// round 3
// speedup vs baseline: 1.3417x; 1.3030x over previous
#include <cuda_runtime.h>

// ---------------------------------------------------------------------------
// ChildSumTreeLSTM, complete binary tree depth 17, D_IN = H = 128. fp32.
// R3: RPT=8 register tiles (1 B smem / FMA2-lane), in-place child-sum,
//     fused 4-gate input GEMM, level-size-matched kernel variants.
// ---------------------------------------------------------------------------

#define DEPTH   17
#define HH      128
#define NNODES  ((1 << (DEPTH + 1)) - 1)        // 262143
#define NH      33554304L                        // NNODES * HH

__device__ float g_X[4 * 33554304L];             // gate-major: i,f,o,u
__device__ float g_h[33554304L];
__device__ float g_c[33554304L];

typedef unsigned long long u64;

__device__ __forceinline__ u64 pk2(float a, float b) {
    u64 r; asm("mov.b64 %0, {%1, %2};" : "=l"(r) : "f"(a), "f"(b)); return r;
}
__device__ __forceinline__ void fma2(u64& d, u64 a, u64 b) {
    asm("fma.rn.f32x2 %0, %1, %2, %0;" : "+l"(d) : "l"(a), "l"(b));
}
__device__ __forceinline__ float2 up2(u64 v) {
    float2 f; asm("mov.b64 {%0, %1}, %2;" : "=f"(f.x), "=f"(f.y) : "l"(v)); return f;
}
__device__ __forceinline__ float sigf(float v)  { return 1.0f / (1.0f + __expf(-v)); }
__device__ __forceinline__ float tanhx(float v) {
    float r; asm("tanh.approx.f32 %0, %1;" : "=f"(r) : "f"(v)); return r;
}

// ---------------------------------------------------------------------------
// Register-tile GEMM: acc[RPT][4] (u64 = 2 cols) = rows @ us.
// Thread rows: row0 + r*rstep in src; cols c0..c0+7.
// SUB=0: plain rows. SUB=1: frag = src[row] - src[row+1] (reconstruct child0).
// ---------------------------------------------------------------------------
template<int RPT, int SUB>
__device__ __forceinline__ void tgemm(u64 acc[RPT][4], const float* __restrict__ src,
                                      int row0, int rstep,
                                      const float* __restrict__ us, int c0)
{
#pragma unroll
    for (int r = 0; r < RPT; ++r) { acc[r][0] = acc[r][1] = acc[r][2] = acc[r][3] = 0ULL; }
#pragma unroll 1
    for (int k0 = 0; k0 < 128; k0 += 4) {
        float4 xv[RPT];
#pragma unroll
        for (int r = 0; r < RPT; ++r) {
            const float* rp = src + (row0 + r * rstep) * HH + k0;
            float4 v = *(const float4*)rp;
            if (SUB) {
                float4 w = *(const float4*)(rp + HH);
                v.x -= w.x; v.y -= w.y; v.z -= w.z; v.w -= w.w;
            }
            xv[r] = v;
        }
#pragma unroll
        for (int kk = 0; kk < 4; ++kk) {
            ulonglong2 wa = *(const ulonglong2*)(us + (k0 + kk) * HH + c0);
            ulonglong2 wb = *(const ulonglong2*)(us + (k0 + kk) * HH + c0 + 4);
#pragma unroll
            for (int r = 0; r < RPT; ++r) {
                float xk = (kk == 0) ? xv[r].x : (kk == 1) ? xv[r].y
                         : (kk == 2) ? xv[r].z : xv[r].w;
                u64 x2 = pk2(xk, xk);
                fma2(acc[r][0], x2, wa.x); fma2(acc[r][1], x2, wa.y);
                fma2(acc[r][2], x2, wb.x); fma2(acc[r][3], x2, wb.y);
            }
        }
    }
}

// ---------------------------------------------------------------------------
// Fused input GEMM: X_g = x @ W_g + b_g for all 4 gates.
// Block tile: 128 nodes x 128 cols; 256 thr = 16 rowgroups(8 rows) x 16 colgrp.
// smem: xs 64 KB + ws 64 KB = 128 KB.
// ---------------------------------------------------------------------------
__global__ void __launch_bounds__(256) gemm_x_kernel(
    const float* __restrict__ x,
    const float* __restrict__ W_i, const float* __restrict__ b_i,
    const float* __restrict__ W_f, const float* __restrict__ b_f,
    const float* __restrict__ W_o, const float* __restrict__ b_o,
    const float* __restrict__ W_u, const float* __restrict__ b_u)
{
    extern __shared__ float sm[];
    float* xs = sm;                 // 128 x 128
    float* ws = sm + 128 * HH;      // 128 x 128

    const int tid = threadIdx.x;
    const int r0  = blockIdx.x * 128;

    for (int f = tid; f < 4096; f += 256) {
        int row = f >> 5, wq = f & 31;
        float4 v = make_float4(0.f, 0.f, 0.f, 0.f);
        if (r0 + row < NNODES)
            v = *(const float4*)(x + (long)(r0 + row) * HH + wq * 4);
        *(float4*)(xs + row * HH + wq * 4) = v;
    }

    const int trow = tid >> 4;
    const int c0   = (tid & 15) * 8;
    const float* Ws[4] = { W_i, W_f, W_o, W_u };
    const float* Bs[4] = { b_i, b_f, b_o, b_u };

    for (int g = 0; g < 4; ++g) {
        __syncthreads();
        for (int f = tid; f < 4096; f += 256)
            ((float4*)ws)[f] = ((const float4*)Ws[g])[f];
        __syncthreads();

        u64 acc[8][4];
        tgemm<8, 0>(acc, xs, trow * 8, 1, ws, c0);

        float4 ba = *(const float4*)(Bs[g] + c0);
        float4 bb = *(const float4*)(Bs[g] + c0 + 4);
        float* out = g_X + (long)g * NH;
#pragma unroll
        for (int r = 0; r < 8; ++r) {
            int row = r0 + trow * 8 + r;
            if (row < NNODES) {
                float2 p0 = up2(acc[r][0]), p1 = up2(acc[r][1]);
                float2 p2 = up2(acc[r][2]), p3 = up2(acc[r][3]);
                *(float4*)(out + (long)row * HH + c0) =
                    make_float4(p0.x + ba.x, p0.y + ba.y, p1.x + ba.z, p1.y + ba.w);
                *(float4*)(out + (long)row * HH + c0 + 4) =
                    make_float4(p2.x + bb.x, p2.y + bb.y, p3.x + bb.z, p3.y + bb.w);
            }
        }
    }
}

// ---------------------------------------------------------------------------
// Leaves: c = sig(Xi)*tanh(Xu); h = sig(Xo)*tanh(c).
// ---------------------------------------------------------------------------
__global__ void leaf_kernel()
{
    const long base = ((1L << DEPTH) - 1) * HH;
    long e = base + ((long)blockIdx.x * blockDim.x + threadIdx.x) * 4;
    float4 xi = *(const float4*)(g_X + e);
    float4 xo = *(const float4*)(g_X + 2 * NH + e);
    float4 xu = *(const float4*)(g_X + 3 * NH + e);
    float4 cv, hv;
    cv.x = sigf(xi.x) * tanhx(xu.x); hv.x = sigf(xo.x) * tanhx(cv.x);
    cv.y = sigf(xi.y) * tanhx(xu.y); hv.y = sigf(xo.y) * tanhx(cv.y);
    cv.z = sigf(xi.z) * tanhx(xu.z); hv.z = sigf(xo.z) * tanhx(cv.z);
    cv.w = sigf(xi.w) * tanhx(xu.w); hv.w = sigf(xo.w) * tanhx(cv.w);
    *(float4*)(g_c + e) = cv;
    *(float4*)(g_h + e) = hv;
}

// ---------------------------------------------------------------------------
// Internal level. TP = 16*RPT parents/block, 256 threads.
// smem: hch (2*TP x 128) + U stage (128 x 128).
// After load, hch[2j] += hch[2j+1] in place: row 2j = h_tilde, 2j+1 = h1,
// child0 = row2j - row2j1 (SUB path, only for the f0 gemm).
// RPT=8 -> 192 KB, RPT=4 -> 128 KB, RPT=2 -> 96 KB.
// ---------------------------------------------------------------------------
template<int RPT>
__global__ void __launch_bounds__(256) level_kernel(
    int sl,
    const float* __restrict__ U_i, const float* __restrict__ U_f,
    const float* __restrict__ U_o, const float* __restrict__ U_u)
{
    constexpr int TP = 16 * RPT;
    extern __shared__ float sm[];
    float* hch = sm;                          // 2*TP x 128
    float* us  = sm + 2 * TP * HH;            // 128 x 128

    const int tid  = threadIdx.x;
    const int trow = tid >> 4;
    const int c0   = (tid & 15) * 8;
    const int p0   = blockIdx.x * TP;
    const long cs  = 2L * sl + 1;
    const long crow0 = cs + 2L * p0;
    const int pl0  = trow * RPT;              // first local parent of this thread

    for (int f = tid; f < 2 * TP * 32; f += 256) {
        int row = f >> 5, wq = f & 31;
        *(float4*)(hch + row * HH + wq * 4) =
            *(const float4*)(g_h + (crow0 + row) * HH + wq * 4);
    }
    __syncthreads();
    // in-place child sum: row 2j <- h0 + h1
    for (int f = tid; f < TP * 32; f += 256) {
        int j = f >> 5, wq = f & 31;
        float4 a = *(const float4*)(hch + (2 * j) * HH + wq * 4);
        float4 b = *(const float4*)(hch + (2 * j + 1) * HH + wq * 4);
        *(float4*)(hch + (2 * j) * HH + wq * 4) =
            make_float4(a.x + b.x, a.y + b.y, a.z + b.z, a.w + b.w);
    }

    u64 acc[RPT][4];
    float cacc[RPT][8];
    float a[8];

#define LOAD_U(SRC) do { __syncthreads();                                   \
        for (int f = tid; f < 4096; f += 256)                               \
            ((float4*)us)[f] = ((const float4*)(SRC))[f];                   \
        __syncthreads(); } while (0)
#define UNP(R) { float2 q0 = up2(acc[R][0]), q1 = up2(acc[R][1]),           \
                        q2 = up2(acc[R][2]), q3 = up2(acc[R][3]);           \
                 a[0]=q0.x; a[1]=q0.y; a[2]=q1.x; a[3]=q1.y;                \
                 a[4]=q2.x; a[5]=q2.y; a[6]=q3.x; a[7]=q3.y; }
#define XG(G, P) (g_X + (long)(G) * NH + (long)(sl + (P)) * HH + c0)

    // ---- u: cacc = tanh(Xu + h~ @ U_u) ----
    LOAD_U(U_u);
    tgemm<RPT, 0>(acc, hch, 2 * pl0, 2, us, c0);
#pragma unroll
    for (int r = 0; r < RPT; ++r) {
        UNP(r);
        const float* xp = XG(3, p0 + pl0 + r);
        float4 xa = *(const float4*)xp, xb = *(const float4*)(xp + 4);
        cacc[r][0] = tanhx(a[0] + xa.x); cacc[r][1] = tanhx(a[1] + xa.y);
        cacc[r][2] = tanhx(a[2] + xa.z); cacc[r][3] = tanhx(a[3] + xa.w);
        cacc[r][4] = tanhx(a[4] + xb.x); cacc[r][5] = tanhx(a[5] + xb.y);
        cacc[r][6] = tanhx(a[6] + xb.z); cacc[r][7] = tanhx(a[7] + xb.w);
    }
    // ---- i: cacc *= sig(Xi + h~ @ U_i) ----
    LOAD_U(U_i);
    tgemm<RPT, 0>(acc, hch, 2 * pl0, 2, us, c0);
#pragma unroll
    for (int r = 0; r < RPT; ++r) {
        UNP(r);
        const float* xp = XG(0, p0 + pl0 + r);
        float4 xa = *(const float4*)xp, xb = *(const float4*)(xp + 4);
        cacc[r][0] *= sigf(a[0] + xa.x); cacc[r][1] *= sigf(a[1] + xa.y);
        cacc[r][2] *= sigf(a[2] + xa.z); cacc[r][3] *= sigf(a[3] + xa.w);
        cacc[r][4] *= sigf(a[4] + xb.x); cacc[r][5] *= sigf(a[5] + xb.y);
        cacc[r][6] *= sigf(a[6] + xb.z); cacc[r][7] *= sigf(a[7] + xb.w);
    }
    // ---- f gates: U_f staged once; child1 plain rows, child0 = h~ - h1 ----
    LOAD_U(U_f);
#pragma unroll
    for (int child = 1; child >= 0; --child) {
        if (child == 1) tgemm<RPT, 0>(acc, hch, 2 * pl0 + 1, 2, us, c0);
        else            tgemm<RPT, 1>(acc, hch, 2 * pl0,     2, us, c0);
#pragma unroll
        for (int r = 0; r < RPT; ++r) {
            UNP(r);
            int p = p0 + pl0 + r;
            const float* xp = XG(1, p);
            float4 xa = *(const float4*)xp, xb = *(const float4*)(xp + 4);
            const float* cp = g_c + (cs + 2L * p + child) * HH + c0;
            float4 ca = *(const float4*)cp, cb = *(const float4*)(cp + 4);
            cacc[r][0] += sigf(a[0] + xa.x) * ca.x;
            cacc[r][1] += sigf(a[1] + xa.y) * ca.y;
            cacc[r][2] += sigf(a[2] + xa.z) * ca.z;
            cacc[r][3] += sigf(a[3] + xa.w) * ca.w;
            cacc[r][4] += sigf(a[4] + xb.x) * cb.x;
            cacc[r][5] += sigf(a[5] + xb.y) * cb.y;
            cacc[r][6] += sigf(a[6] + xb.z) * cb.z;
            cacc[r][7] += sigf(a[7] + xb.w) * cb.w;
        }
    }
    // ---- o + store ----
    LOAD_U(U_o);
    tgemm<RPT, 0>(acc, hch, 2 * pl0, 2, us, c0);
#pragma unroll
    for (int r = 0; r < RPT; ++r) {
        UNP(r);
        long node = sl + p0 + pl0 + r;
        const float* xp = g_X + 2 * NH + node * HH + c0;
        float4 xa = *(const float4*)xp, xb = *(const float4*)(xp + 4);
        float4 cva = make_float4(cacc[r][0], cacc[r][1], cacc[r][2], cacc[r][3]);
        float4 cvb = make_float4(cacc[r][4], cacc[r][5], cacc[r][6], cacc[r][7]);
        float4 hva = make_float4(sigf(a[0] + xa.x) * tanhx(cva.x),
                                 sigf(a[1] + xa.y) * tanhx(cva.y),
                                 sigf(a[2] + xa.z) * tanhx(cva.z),
                                 sigf(a[3] + xa.w) * tanhx(cva.w));
        float4 hvb = make_float4(sigf(a[4] + xb.x) * tanhx(cvb.x),
                                 sigf(a[5] + xb.y) * tanhx(cvb.y),
                                 sigf(a[6] + xb.z) * tanhx(cvb.z),
                                 sigf(a[7] + xb.w) * tanhx(cvb.w));
        *(float4*)(g_c + node * HH + c0)     = cva;
        *(float4*)(g_c + node * HH + c0 + 4) = cvb;
        *(float4*)(g_h + node * HH + c0)     = hva;
        *(float4*)(g_h + node * HH + c0 + 4) = hvb;
    }
#undef LOAD_U
#undef UNP
#undef XG
}

// ---------------------------------------------------------------------------
// Tiny levels (nl <= 256): one parent per block, 512 threads, k-split matvecs.
// ---------------------------------------------------------------------------
__global__ void __launch_bounds__(512) small_level_kernel(
    int sl,
    const float* __restrict__ U_i, const float* __restrict__ U_f,
    const float* __restrict__ U_o, const float* __restrict__ U_u)
{
    __shared__ float hs[3 * 128];            // h~, h0, h1
    __shared__ float part[5][4][128];

    const int t = threadIdx.x;
    const long node = sl + blockIdx.x;
    const long ch0  = 2 * node + 1;

    if (t < 128) {
        float h0 = g_h[ch0 * HH + t];
        float h1 = g_h[(ch0 + 1) * HH + t];
        hs[128 + t] = h0; hs[256 + t] = h1; hs[t] = h0 + h1;
    }
    __syncthreads();

    const int col = t & 127;
    const int kb  = (t >> 7) * 32;
    const int ks  = t >> 7;

#define JOB(J, SOFF, U) { const float* s = hs + (SOFF) * 128; float av = 0.f;  \
        _Pragma("unroll 8")                                                    \
        for (int k = 0; k < 32; ++k) av += s[kb + k] * (U)[(kb + k) * HH + col]; \
        part[J][ks][col] = av; }
    JOB(0, 0, U_i)
    JOB(1, 0, U_o)
    JOB(2, 0, U_u)
    JOB(3, 1, U_f)
    JOB(4, 2, U_f)
#undef JOB
    __syncthreads();

    if (t < 128) {
        float yi  = part[0][0][t] + part[0][1][t] + part[0][2][t] + part[0][3][t];
        float yo  = part[1][0][t] + part[1][1][t] + part[1][2][t] + part[1][3][t];
        float yu  = part[2][0][t] + part[2][1][t] + part[2][2][t] + part[2][3][t];
        float yf0 = part[3][0][t] + part[3][1][t] + part[3][2][t] + part[3][3][t];
        float yf1 = part[4][0][t] + part[4][1][t] + part[4][2][t] + part[4][3][t];
        long e = node * HH + t;
        float xf = g_X[NH + e];
        float iv = sigf(g_X[e] + yi);
        float ov = sigf(g_X[2 * NH + e] + yo);
        float uv = tanhx(g_X[3 * NH + e] + yu);
        float c  = iv * uv + sigf(xf + yf0) * g_c[ch0 * HH + t]
                           + sigf(xf + yf1) * g_c[(ch0 + 1) * HH + t];
        g_c[e] = c;
        g_h[e] = ov * tanhx(c);
    }
}

__global__ void out_kernel(float* __restrict__ out)
{
    int t = threadIdx.x;
    out[t] = (t < 128) ? g_h[t] : g_c[t - 128];
}

// ---------------------------------------------------------------------------
extern "C" void kernel_launch(void* const* d_in, const int* in_sizes, int n_in,
                              void* d_out, int out_size)
{
    const float* x   = (const float*)d_in[0];
    const float* W_i = (const float*)d_in[1];
    const float* b_i = (const float*)d_in[2];
    const float* U_i = (const float*)d_in[3];
    const float* W_f = (const float*)d_in[4];
    const float* b_f = (const float*)d_in[5];
    const float* U_f = (const float*)d_in[6];
    const float* W_o = (const float*)d_in[7];
    const float* b_o = (const float*)d_in[8];
    const float* U_o = (const float*)d_in[9];
    const float* W_u = (const float*)d_in[10];
    const float* b_u = (const float*)d_in[11];
    const float* U_u = (const float*)d_in[12];

    cudaFuncSetAttribute(gemm_x_kernel,   cudaFuncAttributeMaxDynamicSharedMemorySize, 131072);
    cudaFuncSetAttribute(level_kernel<8>, cudaFuncAttributeMaxDynamicSharedMemorySize, 196608);
    cudaFuncSetAttribute(level_kernel<4>, cudaFuncAttributeMaxDynamicSharedMemorySize, 131072);
    cudaFuncSetAttribute(level_kernel<2>, cudaFuncAttributeMaxDynamicSharedMemorySize, 98304);

    gemm_x_kernel<<<(NNODES + 127) / 128, 256, 131072>>>(
        x, W_i, b_i, W_f, b_f, W_o, b_o, W_u, b_u);

    leaf_kernel<<<(1 << DEPTH) * HH / 4 / 256, 256>>>();

    for (int l = DEPTH - 1; l >= 0; --l) {
        int nl = 1 << l;
        int sl = nl - 1;
        if (l >= 14)
            level_kernel<8><<<nl / 128, 256, 196608>>>(sl, U_i, U_f, U_o, U_u);
        else if (l >= 12)
            level_kernel<4><<<nl / 64, 256, 131072>>>(sl, U_i, U_f, U_o, U_u);
        else if (l >= 9)
            level_kernel<2><<<nl / 32, 256, 98304>>>(sl, U_i, U_f, U_o, U_u);
        else
            small_level_kernel<<<nl, 512>>>(sl, U_i, U_f, U_o, U_u);
    }

    out_kernel<<<1, 256>>>((float*)d_out);
}